// round 14
// baseline (speedup 1.0000x reference)
#include <cuda_runtime.h>
#include <cuda_bf16.h>

// Fused SSIM, R9: R4 trunk (4 conv quantities (a,c,ac,a^2+c^2) in float4,
// even/odd deinterleaved smem rows, 2 px/thread, register vertical scatter
// ring, uncapped regs at (128,3)) + 4-row stages (8-slot ring, 36 barriers),
// LDG.64 pair loads, multiply-overwrite recycling, in-kernel ticket reduction.

#define IMG_W 512
#define IMG_H 512
#define PLANE_STRIDE (512*512)
#define NTHR 128
#define NBLOCKS 384          // 48 planes * 2 x-strips * 4 y-bands
#define NSTEPS 138
#define C1_CONST 0.0001f
#define C2_CONST 0.0009f

#define W0 0.00102838f
#define W1 0.00759876f
#define W2 0.03600077f
#define W3 0.10936080f
#define W4 0.21300555f
#define W5 0.26601174f

__device__ float    g_partial[NBLOCKS];
__device__ unsigned g_cnt = 0;

__device__ __forceinline__ float gwt(int k) {
    switch (k) {
        case 0: case 10: return W0;
        case 1: case 9:  return W1;
        case 2: case 8:  return W2;
        case 3: case 7:  return W3;
        case 4: case 6:  return W4;
        default:         return W5;
    }
}

__device__ __forceinline__ void f4fma(float4 &a, const float4 v, const float w) {
    a.x = fmaf(v.x, w, a.x);
    a.y = fmaf(v.y, w, a.y);
    a.z = fmaf(v.z, w, a.z);
    a.w = fmaf(v.w, w, a.w);
}
__device__ __forceinline__ float4 f4scale(const float4 v, const float w) {
    return make_float4(v.x * w, v.y * w, v.z * w, v.w * w);
}

__global__ void __launch_bounds__(NTHR, 3)
ssim_kernel(const float* __restrict__ img1, const float* __restrict__ img2,
            float* __restrict__ out) {
    __shared__ float4 Ev[8][136];
    __shared__ float4 Od[8][136];
    __shared__ float  wsum[4];
    __shared__ int    s_last;

    const int t  = threadIdx.x;
    const int b  = blockIdx.x;
    const int plane = b >> 3;
    const int x0 = (b & 1) * 256;
    const int y0 = ((b >> 1) & 3) * 128;

    const float* p1 = img1 + (size_t)plane * PLANE_STRIDE;
    const float* p2 = img2 + (size_t)plane * PLANE_STRIDE;

    float4 accA[11], accB[11];
#pragma unroll
    for (int j = 0; j < 11; ++j) {
        accA[j] = make_float4(0.f, 0.f, 0.f, 0.f);
        accB[j] = make_float4(0.f, 0.f, 0.f, 0.f);
    }
    float lsum = 0.f;

    // fused loader: LDG.64 pairs -> derived float4 quantities -> STS
    auto load_row = [&](int step) {
        const int  slot = step & 7;
        const int  r    = y0 - 5 + step;
        const bool rok  = ((unsigned)r < (unsigned)IMG_H) && (step < NSTEPS);
        const float* q1 = p1 + (size_t)(rok ? r : 0) * IMG_W;
        const float* q2 = p2 + (size_t)(rok ? r : 0) * IMG_W;
        {
            const int  gx = x0 - 6 + 2 * t;      // even; pair uniform in/out
            const bool ok = rok && ((unsigned)gx < (unsigned)IMG_W);
            const float2 A = ok ? __ldg((const float2*)(q1 + gx)) : make_float2(0.f, 0.f);
            const float2 C = ok ? __ldg((const float2*)(q2 + gx)) : make_float2(0.f, 0.f);
            Ev[slot][t] = make_float4(A.x, C.x, A.x * C.x, fmaf(A.x, A.x, C.x * C.x));
            Od[slot][t] = make_float4(A.y, C.y, A.y * C.y, fmaf(A.y, A.y, C.y * C.y));
        }
        if (t < 6) {                              // tail px 250..261 (rel)
            const int  g2 = x0 + 250 + 2 * t;
            const bool ok = rok && (g2 < IMG_W);
            const float2 A = ok ? __ldg((const float2*)(q1 + g2)) : make_float2(0.f, 0.f);
            const float2 C = ok ? __ldg((const float2*)(q2 + g2)) : make_float2(0.f, 0.f);
            Ev[slot][128 + t] = make_float4(A.x, C.x, A.x * C.x, fmaf(A.x, A.x, C.x * C.x));
            Od[slot][128 + t] = make_float4(A.y, C.y, A.y * C.y, fmaf(A.y, A.y, C.y * C.y));
        }
    };

    auto epi = [&](const float4 q) {   // q = (mu1, mu2, e12, e11+e22)
        const float m11 = q.x * q.x;
        const float m22 = q.y * q.y;
        const float m12 = q.x * q.y;
        const float num = (2.f * m12 + C1_CONST) * (2.f * (q.z - m12) + C2_CONST);
        const float den = (m11 + m22 + C1_CONST) * ((q.w - m11 - m22) + C2_CONST);
        lsum += __fdividef(num, den);
    };

#define PROC(SV, RR) {                                                         \
    const int sl_ = (SV) & 7;                                                  \
    const float4* ev = Ev[sl_];                                                \
    const float4* od = Od[sl_];                                                \
    float4 hA = make_float4(0.f, 0.f, 0.f, 0.f);                               \
    float4 hB = make_float4(0.f, 0.f, 0.f, 0.f);                               \
    float4 v_;                                                                 \
    v_ = od[t];     f4fma(hA, v_, W0);                                         \
    v_ = ev[t + 1]; f4fma(hA, v_, W1); f4fma(hB, v_, W0);                      \
    v_ = od[t + 1]; f4fma(hA, v_, W2); f4fma(hB, v_, W1);                      \
    v_ = ev[t + 2]; f4fma(hA, v_, W3); f4fma(hB, v_, W2);                      \
    v_ = od[t + 2]; f4fma(hA, v_, W4); f4fma(hB, v_, W3);                      \
    v_ = ev[t + 3]; f4fma(hA, v_, W5); f4fma(hB, v_, W4);                      \
    v_ = od[t + 3]; f4fma(hA, v_, W4); f4fma(hB, v_, W5);                      \
    v_ = ev[t + 4]; f4fma(hA, v_, W3); f4fma(hB, v_, W4);                      \
    v_ = od[t + 4]; f4fma(hA, v_, W2); f4fma(hB, v_, W3);                      \
    v_ = ev[t + 5]; f4fma(hA, v_, W1); f4fma(hB, v_, W2);                      \
    v_ = od[t + 5]; f4fma(hA, v_, W0); f4fma(hB, v_, W1);                      \
    v_ = ev[t + 6];                    f4fma(hB, v_, W0);                      \
    _Pragma("unroll")                                                          \
    for (int j = 0; j < 10; ++j) {                                             \
        const float wj = gwt(j);                                               \
        const int sl = ((RR) + j) % 11;                                        \
        f4fma(accA[sl], hA, wj);                                               \
        f4fma(accB[sl], hB, wj);                                               \
    }                                                                          \
    {   /* j=10: first tap of freshly recycled slot -> overwrite */            \
        const int sl = ((RR) + 10) % 11;                                       \
        accA[sl] = f4scale(hA, W0);                                            \
        accB[sl] = f4scale(hB, W0);                                            \
    }                                                                          \
    if ((SV) >= 10) { epi(accA[RR]); epi(accB[RR]); }                          \
}

    // prologue: rows 0..3
    load_row(0); load_row(1); load_row(2); load_row(3);
    __syncthreads();

    int s = 0;
#pragma unroll 1
    for (int blk = 0; blk < 3; ++blk) {          // 3 * 11 stages * 4 rows = 132
#pragma unroll
        for (int it = 0; it < 11; ++it) {        // s % 11 == (4*it) % 11
            load_row(s + 4); load_row(s + 5); load_row(s + 6); load_row(s + 7);
            PROC(s,     (4 * it)     % 11);
            PROC(s + 1, (4 * it + 1) % 11);
            PROC(s + 2, (4 * it + 2) % 11);
            PROC(s + 3, (4 * it + 3) % 11);
            __syncthreads();
            s += 4;
        }
    }
    // rows 132..135 (132 % 11 == 0)
    load_row(s + 4); load_row(s + 5);
    PROC(s,     0);
    PROC(s + 1, 1);
    PROC(s + 2, 2);
    PROC(s + 3, 3);
    __syncthreads();
    s += 4;
    // rows 136..137 (136 % 11 == 4)
    PROC(s,     4);
    PROC(s + 1, 5);
#undef PROC

    // deterministic per-CTA partial (4 warps)
    float v = lsum;
#pragma unroll
    for (int o = 16; o; o >>= 1) v += __shfl_xor_sync(0xffffffffu, v, o);
    if ((t & 31) == 0) wsum[t >> 5] = v;
    __syncthreads();
    if (t == 0) {
        g_partial[b] = (wsum[0] + wsum[1]) + (wsum[2] + wsum[3]);
        __threadfence();
        const unsigned tk = atomicInc(&g_cnt, NBLOCKS - 1);  // self-resetting
        s_last = (tk == NBLOCKS - 1);
    }
    __syncthreads();

    // last CTA: deterministic final reduction over 384 partials
    if (s_last) {
        float sv = __ldcg(&g_partial[t]) + __ldcg(&g_partial[t + 128]) +
                   __ldcg(&g_partial[t + 256]);
#pragma unroll
        for (int o = 16; o; o >>= 1) sv += __shfl_xor_sync(0xffffffffu, sv, o);
        if ((t & 31) == 0) wsum[t >> 5] = sv;
        __syncthreads();
        if (t == 0) {
            out[0] = ((wsum[0] + wsum[1]) + (wsum[2] + wsum[3])) *
                     (1.0f / 12582912.0f);
        }
    }
}

extern "C" void kernel_launch(void* const* d_in, const int* in_sizes, int n_in,
                              void* d_out, int out_size) {
    const float* img1 = (const float*)d_in[0];
    const float* img2 = (const float*)d_in[1];
    (void)in_sizes; (void)n_in; (void)out_size;
    ssim_kernel<<<NBLOCKS, NTHR>>>(img1, img2, (float*)d_out);
}

// round 15
// speedup vs baseline: 1.1550x; 1.1550x over previous
#include <cuda_runtime.h>
#include <cuda_bf16.h>

// Fused SSIM, R10: exact R4 trunk (verified 117.5us) with ONE change:
// final reduction folded into the main kernel via last-CTA ticket
// (removes the 4.2us standalone reduce kernel).

#define IMG_W 512
#define IMG_H 512
#define PLANE_STRIDE (512*512)
#define BW 256               // output strip width per CTA
#define NTHR 128             // threads per CTA (2 px each)
#define NBLOCKS 384          // 48 planes * 2x4 tiles
#define NSTEPS 138
#define C1_CONST 0.0001f
#define C2_CONST 0.0009f

#define W0 0.00102838f
#define W1 0.00759876f
#define W2 0.03600077f
#define W3 0.10936080f
#define W4 0.21300555f
#define W5 0.26601174f

__device__ float    g_partial[NBLOCKS];
__device__ unsigned g_cnt = 0;

__device__ __forceinline__ float gwt(int k) {
    switch (k) {
        case 0: case 10: return W0;
        case 1: case 9:  return W1;
        case 2: case 8:  return W2;
        case 3: case 7:  return W3;
        case 4: case 6:  return W4;
        default:         return W5;
    }
}

__device__ __forceinline__ void f4fma(float4 &a, const float4 v, const float w) {
    a.x = fmaf(v.x, w, a.x);
    a.y = fmaf(v.y, w, a.y);
    a.z = fmaf(v.z, w, a.z);
    a.w = fmaf(v.w, w, a.w);
}

__global__ void __launch_bounds__(NTHR, 3)
ssim_kernel(const float* __restrict__ img1, const float* __restrict__ img2,
            float* __restrict__ out) {
    // 4-row ring; input px p (relative): even p -> Ev[(p+6)/2], odd p -> Od[(p+5)/2]
    __shared__ float4 Ev[4][136];
    __shared__ float4 Od[4][136];
    __shared__ float  wsum[4];
    __shared__ int    s_last;

    const int t  = threadIdx.x;
    const int b  = blockIdx.x;
    const int plane = b >> 3;             // 8 tiles per plane
    const int x0 = (b & 1) * BW;
    const int y0 = ((b >> 1) & 3) * 128;

    const float* p1 = img1 + (size_t)plane * PLANE_STRIDE;
    const float* p2 = img2 + (size_t)plane * PLANE_STRIDE;

    // vertical scatter rings for the two output columns (2t, 2t+1)
    float4 accA[11], accB[11];
#pragma unroll
    for (int j = 0; j < 11; ++j) {
        accA[j] = make_float4(0.f, 0.f, 0.f, 0.f);
        accB[j] = make_float4(0.f, 0.f, 0.f, 0.f);
    }
    float lsum = 0.f;

    auto load_row = [&](int step) {
        const int slot = step & 3;
        const int r    = y0 - 5 + step;
        const bool rok = ((unsigned)r < (unsigned)IMG_H) && (step < NSTEPS);
        const float* q1 = p1 + (size_t)(rok ? r : 0) * IMG_W;
        const float* q2 = p2 + (size_t)(rok ? r : 0) * IMG_W;
        {
            const int gx = x0 - 6 + 2 * t;          // even px = 2t-6 (rel)
            const bool k0 = rok && ((unsigned)gx       < (unsigned)IMG_W);
            const bool k1 = rok && ((unsigned)(gx + 1) < (unsigned)IMG_W);
            const float a0 = k0 ? __ldg(q1 + gx)     : 0.f;
            const float c0 = k0 ? __ldg(q2 + gx)     : 0.f;
            const float a1 = k1 ? __ldg(q1 + gx + 1) : 0.f;
            const float c1 = k1 ? __ldg(q2 + gx + 1) : 0.f;
            Ev[slot][t] = make_float4(a0, c0, a0 * c0, fmaf(a0, a0, c0 * c0));
            Od[slot][t] = make_float4(a1, c1, a1 * c1, fmaf(a1, a1, c1 * c1));
        }
        if (t < 6) {                                 // tail px 250..261 (rel)
            const int gx = x0 + 250 + 2 * t;
            const bool k0 = rok && (gx     < IMG_W);
            const bool k1 = rok && (gx + 1 < IMG_W);
            const float a0 = k0 ? __ldg(q1 + gx)     : 0.f;
            const float c0 = k0 ? __ldg(q2 + gx)     : 0.f;
            const float a1 = k1 ? __ldg(q1 + gx + 1) : 0.f;
            const float c1 = k1 ? __ldg(q2 + gx + 1) : 0.f;
            Ev[slot][128 + t] = make_float4(a0, c0, a0 * c0, fmaf(a0, a0, c0 * c0));
            Od[slot][128 + t] = make_float4(a1, c1, a1 * c1, fmaf(a1, a1, c1 * c1));
        }
    };

    auto epi = [&](const float4 q) {   // q = (mu1, mu2, e12, e11+e22)
        const float m11 = q.x * q.x;
        const float m22 = q.y * q.y;
        const float m12 = q.x * q.y;
        const float num = (2.f * m12 + C1_CONST) * (2.f * (q.z - m12) + C2_CONST);
        const float den = (m11 + m22 + C1_CONST) * ((q.w - m11 - m22) + C2_CONST);
        lsum += __fdividef(num, den);
    };

#define PROC(SV, RR) {                                                         \
    const int sl_ = (SV) & 3;                                                  \
    const float4* ev = Ev[sl_];                                                \
    const float4* od = Od[sl_];                                                \
    float4 hA = make_float4(0.f, 0.f, 0.f, 0.f);                               \
    float4 hB = make_float4(0.f, 0.f, 0.f, 0.f);                               \
    float4 v_;                                                                 \
    v_ = od[t];     f4fma(hA, v_, W0);                                         \
    v_ = ev[t + 1]; f4fma(hA, v_, W1); f4fma(hB, v_, W0);                      \
    v_ = od[t + 1]; f4fma(hA, v_, W2); f4fma(hB, v_, W1);                      \
    v_ = ev[t + 2]; f4fma(hA, v_, W3); f4fma(hB, v_, W2);                      \
    v_ = od[t + 2]; f4fma(hA, v_, W4); f4fma(hB, v_, W3);                      \
    v_ = ev[t + 3]; f4fma(hA, v_, W5); f4fma(hB, v_, W4);                      \
    v_ = od[t + 3]; f4fma(hA, v_, W4); f4fma(hB, v_, W5);                      \
    v_ = ev[t + 4]; f4fma(hA, v_, W3); f4fma(hB, v_, W4);                      \
    v_ = od[t + 4]; f4fma(hA, v_, W2); f4fma(hB, v_, W3);                      \
    v_ = ev[t + 5]; f4fma(hA, v_, W1); f4fma(hB, v_, W2);                      \
    v_ = od[t + 5]; f4fma(hA, v_, W0); f4fma(hB, v_, W1);                      \
    v_ = ev[t + 6];                    f4fma(hB, v_, W0);                      \
    _Pragma("unroll")                                                          \
    for (int j = 0; j < 11; ++j) {                                             \
        const float w = gwt(j);                                                \
        const int sl = ((RR) + j) % 11;                                        \
        f4fma(accA[sl], hA, w);                                                \
        f4fma(accB[sl], hB, w);                                                \
    }                                                                          \
    if ((SV) >= 10) { epi(accA[RR]); epi(accB[RR]); }                          \
    accA[RR] = make_float4(0.f, 0.f, 0.f, 0.f);                                \
    accB[RR] = make_float4(0.f, 0.f, 0.f, 0.f);                                \
}

    load_row(0);
    load_row(1);

    int s = 0;
#pragma unroll 1
    for (int blk = 0; blk < 6; ++blk) {          // 6 * 22 = 132 rows
#pragma unroll
        for (int it = 0; it < 11; ++it) {
            __syncthreads();
            load_row(s + 2);
            load_row(s + 3);
            PROC(s,     (2 * it) % 11);
            PROC(s + 1, (2 * it + 1) % 11);
            s += 2;
        }
    }
#pragma unroll
    for (int it = 0; it < 3; ++it) {             // rows 132..137
        __syncthreads();
        load_row(s + 2);
        load_row(s + 3);
        PROC(s,     2 * it);
        PROC(s + 1, 2 * it + 1);
        s += 2;
    }
#undef PROC

    // deterministic per-CTA partial (4 warps)
    float v = lsum;
#pragma unroll
    for (int o = 16; o; o >>= 1) v += __shfl_xor_sync(0xffffffffu, v, o);
    if ((t & 31) == 0) wsum[t >> 5] = v;
    __syncthreads();
    if (t == 0) {
        g_partial[b] = (wsum[0] + wsum[1]) + (wsum[2] + wsum[3]);
        __threadfence();
        const unsigned tk = atomicInc(&g_cnt, NBLOCKS - 1);  // self-resetting
        s_last = (tk == NBLOCKS - 1);
    }
    __syncthreads();

    // last CTA: deterministic final reduction over 384 partials
    if (s_last) {
        float sv = __ldcg(&g_partial[t]) + __ldcg(&g_partial[t + 128]) +
                   __ldcg(&g_partial[t + 256]);
#pragma unroll
        for (int o = 16; o; o >>= 1) sv += __shfl_xor_sync(0xffffffffu, sv, o);
        if ((t & 31) == 0) wsum[t >> 5] = sv;
        __syncthreads();
        if (t == 0) {
            out[0] = ((wsum[0] + wsum[1]) + (wsum[2] + wsum[3])) *
                     (1.0f / 12582912.0f);
        }
    }
}

extern "C" void kernel_launch(void* const* d_in, const int* in_sizes, int n_in,
                              void* d_out, int out_size) {
    const float* img1 = (const float*)d_in[0];
    const float* img2 = (const float*)d_in[1];
    (void)in_sizes; (void)n_in; (void)out_size;
    ssim_kernel<<<NBLOCKS, NTHR>>>(img1, img2, (float*)d_out);
}